// round 2
// baseline (speedup 1.0000x reference)
#include <cuda_runtime.h>
#include <math.h>
#include <float.h>

#define NN 100000
#define EE 3200000
#define IND 64
#define HID 128
#define NCLS 10

// ---------------- scratch (device globals; no runtime allocation) ----------
__device__ float d_h1[(size_t)NN * HID];   // relu(A1@W1 + rs*b1)    [N,128]
__device__ float d_h [(size_t)NN * HID];   // h1 + relu(A2@W2+rs*b2) [N,128]
__device__ float d_s [NN];                 // attention scores
__device__ float d_rowsum[NN];             // adj @ 1
__device__ int   d_rowptr[NN + 1];
__device__ float d_g[HID];
__device__ float d_Z;
__device__ float d_max;

// ---------------- helpers ---------------------------------------------------
__device__ __forceinline__ void atomicMaxFloat(float* addr, float val) {
    int* ia = (int*)addr;
    int old = *ia;
    while (__int_as_float(old) < val) {
        int assumed = old;
        old = atomicCAS(ia, assumed, __float_as_int(val));
        if (old == assumed) break;
    }
}

__device__ __forceinline__ unsigned long long pack2(float a) {
    unsigned long long r;
    asm("mov.b64 %0, {%1, %1};" : "=l"(r) : "f"(a));
    return r;
}
__device__ __forceinline__ void fma2(unsigned long long& d,
                                     unsigned long long a, unsigned long long b) {
    asm("fma.rn.f32x2 %0, %1, %2, %0;" : "+l"(d) : "l"(a), "l"(b));
}
__device__ __forceinline__ void unpack2(unsigned long long v, float& lo, float& hi) {
    asm("mov.b64 {%0, %1}, %2;" : "=f"(lo), "=f"(hi) : "l"(v));
}

// ---------------- kernel 0: rowptr scatter + accumulator init ---------------
__global__ void k_rowptr(const int* __restrict__ erows) {
    int i = blockIdx.x * blockDim.x + threadIdx.x;
    if (i < HID) d_g[i] = 0.f;
    if (i == HID)     d_Z = 0.f;
    if (i == HID + 1) d_max = -FLT_MAX;
    if (i >= EE) return;
    int r1 = erows[i];
    int r0 = (i == 0) ? -1 : erows[i - 1];
    for (int r = r0 + 1; r <= r1; r++) d_rowptr[r] = i;
    if (i == EE - 1)
        for (int r = r1 + 1; r <= NN; r++) d_rowptr[r] = EE;
}

// ---------------- fused SpMM + GEMM ------------------------------------------
// Per block: 128 rows.
// Phase 1 (SpMM): warp-per-row gather of src (width K) into smem A-tile.
// Phase 2 (GEMM): C[128,128] = A[128,K] @ W[K,128] using fma.rn.f32x2.
// Epilogue: relu(acc + rowsum*b); SECOND also adds h1, computes attention
// scores s = h @ att_w + att_b, and the global max.
template <int K, bool SECOND>
__global__ void __launch_bounds__(256, 2)
k_fused(const float* __restrict__ src,
        const float* __restrict__ W,
        const float* __restrict__ bias,
        float* __restrict__ Cout,
        const int* __restrict__ cols,
        const float* __restrict__ vals,
        const float* __restrict__ att_w,
        const float* __restrict__ att_b) {
    extern __shared__ float sm[];
    float* A_sh  = sm;                  // 128*K
    float* W_sh  = sm + 128 * K;        // 16*128
    float* rs_sh = W_sh + 16 * 128;     // 128
    float* aw_sh = rs_sh + 128;         // 128
    float* smax  = aw_sh + 128;         // 16

    const int tid = threadIdx.x;
    const int r0 = blockIdx.x * 128;
    constexpr int V = K / 32;           // floats per lane in the gather

    if (SECOND && tid < 128) aw_sh[tid] = att_w[tid];

    // ---------- phase 1: SpMM into A_sh ----------
    {
        int wid = tid >> 5, lane = tid & 31;
        for (int rr = 0; rr < 16; rr++) {
            int rl = wid * 16 + rr;
            int row = r0 + rl;
            float acc[V];
#pragma unroll
            for (int j = 0; j < V; j++) acc[j] = 0.f;
            float vs = 0.f;
            if (row < NN) {
                int s = d_rowptr[row], e = d_rowptr[row + 1];
                int i = s;
                for (; i + 4 <= e; i += 4) {
                    float v[4]; int c[4];
#pragma unroll
                    for (int u = 0; u < 4; u++) {
                        v[u] = __ldg(vals + i + u);
                        c[u] = __ldg(cols + i + u);
                    }
#pragma unroll
                    for (int u = 0; u < 4; u++) {
                        const float* p = src + (size_t)c[u] * K + lane * V;
                        if (V == 4) {
                            float4 xv = *(const float4*)p;
                            acc[0] += v[u] * xv.x; acc[1] += v[u] * xv.y;
                            acc[2] += v[u] * xv.z; acc[3] += v[u] * xv.w;
                        } else {
                            float2 xv = *(const float2*)p;
                            acc[0] += v[u] * xv.x; acc[1] += v[u] * xv.y;
                        }
                        vs += v[u];
                    }
                }
                for (; i < e; i++) {
                    float v = __ldg(vals + i);
                    int   c = __ldg(cols + i);
                    const float* p = src + (size_t)c * K + lane * V;
                    if (V == 4) {
                        float4 xv = *(const float4*)p;
                        acc[0] += v * xv.x; acc[1] += v * xv.y;
                        acc[2] += v * xv.z; acc[3] += v * xv.w;
                    } else {
                        float2 xv = *(const float2*)p;
                        acc[0] += v * xv.x; acc[1] += v * xv.y;
                    }
                    vs += v;
                }
            }
            if (V == 4) {
                *(float4*)&A_sh[rl * K + lane * 4] =
                    make_float4(acc[0], acc[1], acc[2], acc[3]);
            } else {
                *(float2*)&A_sh[rl * K + lane * 2] = make_float2(acc[0], acc[1]);
            }
            if (!SECOND && lane == 0) {
                rs_sh[rl] = vs;
                if (row < NN) d_rowsum[row] = vs;
            }
        }
    }
    __syncthreads();

    // ---------- phase 2: GEMM ----------
    const int tx = tid & 15, ty = tid >> 4;   // thread tile: rows ty*8.., cols tx*8..
    unsigned long long accp[8][4];
#pragma unroll
    for (int r = 0; r < 8; r++)
#pragma unroll
        for (int jp = 0; jp < 4; jp++) accp[r][jp] = 0ull;

    for (int k0 = 0; k0 < K; k0 += 16) {
        if (k0) __syncthreads();
        {
            int wr = tid >> 4;
            int wc = (tid & 15) * 8;
            const float* wp = W + (size_t)(k0 + wr) * HID + wc;
            *(float4*)&W_sh[wr * 128 + wc]     = *(const float4*)wp;
            *(float4*)&W_sh[wr * 128 + wc + 4] = *(const float4*)(wp + 4);
        }
        __syncthreads();
#pragma unroll
        for (int kk = 0; kk < 16; kk++) {
            unsigned long long w2[4];
#pragma unroll
            for (int jp = 0; jp < 4; jp++)
                w2[jp] = *(const unsigned long long*)&W_sh[kk * 128 + tx * 8 + jp * 2];
#pragma unroll
            for (int r = 0; r < 8; r++) {
                unsigned long long a2 = pack2(A_sh[(ty * 8 + r) * K + k0 + kk]);
#pragma unroll
                for (int jp = 0; jp < 4; jp++) fma2(accp[r][jp], a2, w2[jp]);
            }
        }
    }

    // ---------- epilogue ----------
    float4 b0 = *(const float4*)(bias + tx * 8);
    float4 b1 = *(const float4*)(bias + tx * 8 + 4);
    float bb[8] = {b0.x, b0.y, b0.z, b0.w, b1.x, b1.y, b1.z, b1.w};
    float p[8];
#pragma unroll
    for (int r = 0; r < 8; r++) p[r] = 0.f;

#pragma unroll
    for (int r = 0; r < 8; r++) {
        int gr = r0 + ty * 8 + r;
        if (gr >= NN) continue;
        float rs = SECOND ? d_rowsum[gr] : rs_sh[ty * 8 + r];
        float o[8];
#pragma unroll
        for (int jp = 0; jp < 4; jp++)
            unpack2(accp[r][jp], o[jp * 2], o[jp * 2 + 1]);
        float res[8];
#pragma unroll
        for (int j = 0; j < 8; j++) res[j] = fmaxf(o[j] + rs * bb[j], 0.f);
        if (SECOND) {
            const float* h1p = d_h1 + (size_t)gr * HID + tx * 8;
            float4 ha = *(const float4*)h1p;
            float4 hc = *(const float4*)(h1p + 4);
            res[0] += ha.x; res[1] += ha.y; res[2] += ha.z; res[3] += ha.w;
            res[4] += hc.x; res[5] += hc.y; res[6] += hc.z; res[7] += hc.w;
            float pr = 0.f;
#pragma unroll
            for (int j = 0; j < 8; j++) pr += res[j] * aw_sh[tx * 8 + j];
            p[r] = pr;
        }
        float* cp = Cout + (size_t)gr * HID + tx * 8;
        *(float4*)cp       = make_float4(res[0], res[1], res[2], res[3]);
        *(float4*)(cp + 4) = make_float4(res[4], res[5], res[6], res[7]);
    }

    if (SECOND) {
        // reduce p[r] across the 16 tx lanes (two independent 16-lane halves)
#pragma unroll
        for (int r = 0; r < 8; r++) {
#pragma unroll
            for (int off = 1; off < 16; off <<= 1)
                p[r] += __shfl_xor_sync(0xFFFFFFFFu, p[r], off);
        }
        if (tx == 0) {
            float ab = att_b[0];
            float m = -FLT_MAX;
#pragma unroll
            for (int r = 0; r < 8; r++) {
                int gr = r0 + ty * 8 + r;
                if (gr < NN) {
                    float sc = p[r] + ab;
                    d_s[gr] = sc;
                    m = fmaxf(m, sc);
                }
            }
            smax[ty] = m;
        }
        __syncthreads();
        if (tid == 0) {
            float m = smax[0];
#pragma unroll
            for (int i = 1; i < 16; i++) m = fmaxf(m, smax[i]);
            atomicMaxFloat(&d_max, m);
        }
    }
}

// ---------------- weighted pool: Z and g = sum exp(s-m)*h --------------------
__global__ void k_weighted() {
    __shared__ float gsh[128];
    __shared__ float zsh;
    int tid = threadIdx.x, lane = tid & 31, wid = tid >> 5;
    if (tid < 128) gsh[tid] = 0.f;
    if (tid == 128) zsh = 0.f;
    __syncthreads();
    int nwarps = gridDim.x * (blockDim.x >> 5);
    int gw = blockIdx.x * (blockDim.x >> 5) + wid;
    float m = d_max;
    float4 acc = make_float4(0.f, 0.f, 0.f, 0.f);
    float zacc = 0.f;
    const float4* h4 = (const float4*)d_h;
    for (int row = gw; row < NN; row += nwarps) {
        float e = expf(d_s[row] - m);
        float4 h = h4[(size_t)row * 32 + lane];
        acc.x += e * h.x;
        acc.y += e * h.y;
        acc.z += e * h.z;
        acc.w += e * h.w;
        if (lane == 0) zacc += e;
    }
    atomicAdd(&gsh[lane * 4 + 0], acc.x);
    atomicAdd(&gsh[lane * 4 + 1], acc.y);
    atomicAdd(&gsh[lane * 4 + 2], acc.z);
    atomicAdd(&gsh[lane * 4 + 3], acc.w);
    if (lane == 0) atomicAdd(&zsh, zacc);
    __syncthreads();
    if (tid < 128) atomicAdd(&d_g[tid], gsh[tid]);
    if (tid == 128) atomicAdd(&d_Z, zsh);
}

// ---------------- final: out = (g/Z) @ cls_w + cls_b -------------------------
__global__ void k_final(const float* __restrict__ cls_w,
                        const float* __restrict__ cls_b,
                        float* __restrict__ out) {
    int c = threadIdx.x;
    if (c < NCLS) {
        float invZ = 1.f / d_Z;
        float acc = cls_b[c];
        for (int k = 0; k < HID; k++)
            acc += (d_g[k] * invZ) * cls_w[k * NCLS + c];
        out[c] = acc;
    }
}

// ---------------- launch ------------------------------------------------------
extern "C" void kernel_launch(void* const* d_in, const int* in_sizes, int n_in,
                              void* d_out, int out_size) {
    const float* x     = (const float*)d_in[0];
    const int*   erows = (const int*)  d_in[1];
    const int*   ecols = (const int*)  d_in[2];
    const float* evals = (const float*)d_in[3];
    const float* fc1_w = (const float*)d_in[4];
    const float* fc1_b = (const float*)d_in[5];
    const float* fc2_w = (const float*)d_in[6];
    const float* fc2_b = (const float*)d_in[7];
    const float* att_w = (const float*)d_in[8];
    const float* att_b = (const float*)d_in[9];
    const float* cls_w = (const float*)d_in[10];
    const float* cls_b = (const float*)d_in[11];
    float* out = (float*)d_out;

    float* pH1 = nullptr; float* pH = nullptr;
    cudaGetSymbolAddress((void**)&pH1, d_h1);
    cudaGetSymbolAddress((void**)&pH,  d_h);

    const int smem1 = (128 * IND + 16 * 128 + 128 + 128 + 16) * 4;
    const int smem2 = (128 * HID + 16 * 128 + 128 + 128 + 16) * 4;
    static bool attr_done = false;
    if (!attr_done) {
        cudaFuncSetAttribute(k_fused<IND, false>,
                             cudaFuncAttributeMaxDynamicSharedMemorySize, smem1);
        cudaFuncSetAttribute(k_fused<HID, true>,
                             cudaFuncAttributeMaxDynamicSharedMemorySize, smem2);
        attr_done = true;
    }

    int nblk = (NN + 127) / 128;
    k_rowptr<<<(EE + 255) / 256, 256>>>(erows);
    k_fused<IND, false><<<nblk, 256, smem1>>>(x, fc1_w, fc1_b, pH1,
                                              ecols, evals, nullptr, nullptr);
    k_fused<HID, true><<<nblk, 256, smem2>>>(pH1, fc2_w, fc2_b, pH,
                                             ecols, evals, att_w, att_b);
    k_weighted<<<1184, 256>>>();
    k_final<<<1, 32>>>(cls_w, cls_b, out);
}

// round 3
// speedup vs baseline: 1.4661x; 1.4661x over previous
#include <cuda_runtime.h>
#include <math.h>
#include <float.h>

#define NN 100000
#define EE 3200000
#define IND 64
#define HID 128
#define NCLS 10
#define NB ((NN + 127) / 128)

// ---------------- scratch (device globals) ----------------------------------
__device__ float d_A1[(size_t)NN * IND];    // adj @ x            [N,64]
__device__ float d_h1[(size_t)NN * HID];    // layer-1 output     [N,128]
__device__ float d_A2[(size_t)NN * HID];    // adj @ h1           [N,128]
__device__ float d_rowsum[NN];
__device__ int   d_rowptr[NN + 1];
__device__ float d_part[(size_t)NB * 130];  // per-block g[128], Z, m
__device__ float d_g[HID];
__device__ float d_Z;

// ---------------- helpers ----------------------------------------------------
__device__ __forceinline__ unsigned long long pack2(float a) {
    unsigned long long r;
    asm("mov.b64 %0, {%1, %1};" : "=l"(r) : "f"(a));
    return r;
}
__device__ __forceinline__ void fma2(unsigned long long& d,
                                     unsigned long long a, unsigned long long b) {
    asm("fma.rn.f32x2 %0, %1, %2, %0;" : "+l"(d) : "l"(a), "l"(b));
}
__device__ __forceinline__ void unpack2(unsigned long long v, float& lo, float& hi) {
    asm("mov.b64 {%0, %1}, %2;" : "=f"(lo), "=f"(hi) : "l"(v));
}

// ---------------- kernel 0: rowptr scatter -----------------------------------
__global__ void k_rowptr(const int* __restrict__ erows) {
    int i = blockIdx.x * blockDim.x + threadIdx.x;
    if (i >= EE) return;
    int r1 = erows[i];
    int r0 = (i == 0) ? -1 : erows[i - 1];
    for (int r = r0 + 1; r <= r1; r++) d_rowptr[r] = i;
    if (i == EE - 1)
        for (int r = r1 + 1; r <= NN; r++) d_rowptr[r] = EE;
}

// ---------------- SpMM (warp per row), 64-wide + rowsum ----------------------
__global__ void k_spmm64(const float* __restrict__ mat,
                         const int* __restrict__ cols,
                         const float* __restrict__ vals) {
    int row = blockIdx.x * 8 + (threadIdx.x >> 5);
    if (row >= NN) return;
    int lane = threadIdx.x & 31;
    int s = d_rowptr[row], e = d_rowptr[row + 1];
    float2 acc = make_float2(0.f, 0.f);
    float vs = 0.f;
    const float2* m2 = (const float2*)mat;
    for (int i = s; i < e; i++) {
        float v = __ldg(vals + i);
        int   c = __ldg(cols + i);
        float2 xv = m2[(size_t)c * 32 + lane];
        acc.x += v * xv.x;
        acc.y += v * xv.y;
        vs += v;
    }
    ((float2*)d_A1)[(size_t)row * 32 + lane] = acc;
    if (lane == 0) d_rowsum[row] = vs;
}

// ---------------- SpMM (warp per row), 128-wide ------------------------------
__global__ void k_spmm128(const int* __restrict__ cols,
                          const float* __restrict__ vals) {
    int row = blockIdx.x * 8 + (threadIdx.x >> 5);
    if (row >= NN) return;
    int lane = threadIdx.x & 31;
    int s = d_rowptr[row], e = d_rowptr[row + 1];
    float4 acc = make_float4(0.f, 0.f, 0.f, 0.f);
    const float4* m4 = (const float4*)d_h1;
    for (int i = s; i < e; i++) {
        float v = __ldg(vals + i);
        int   c = __ldg(cols + i);
        float4 xv = m4[(size_t)c * 32 + lane];
        acc.x += v * xv.x;
        acc.y += v * xv.y;
        acc.z += v * xv.z;
        acc.w += v * xv.w;
    }
    ((float4*)d_A2)[(size_t)row * 32 + lane] = acc;
}

// ---------------- GEMM: 128x128 tile, f32x2, swizzled transposed A -----------
// C[N,128] = epilogue(A[N,K] @ W[K,128])
//   !SECOND: d_h1 = relu(acc + rowsum*b)
//    SECOND: h = h1 + relu(acc + rowsum*b); per-block softmax-pool partials.
template <int K, bool SECOND>
__global__ void __launch_bounds__(256, 2)
k_gemm(const float* __restrict__ A,
       const float* __restrict__ W,
       const float* __restrict__ bias,
       const float* __restrict__ att_w,
       const float* __restrict__ att_b) {
    extern __shared__ float sm[];
    float* A_shT = sm;                    // K*128, swizzled
    float* W_sh  = sm + K * 128;          // 16*128
    float* aw_sh = W_sh + 16 * 128;       // 128
    float* s_sh  = aw_sh + 128;           // 128
    float* g_sh  = s_sh + 128;            // 128
    float* wmax  = g_sh + 128;            // 8
    float* m_sh  = wmax + 8;              // 1
    float* z_sh  = m_sh + 1;              // 1

    const int tid = threadIdx.x;
    const int r0 = blockIdx.x * 128;
    const int tx = tid & 15, ty = tid >> 4;
    const int txc = tx * 8;

    if (SECOND) {
        if (tid < 128) { aw_sh[tid] = att_w[tid]; g_sh[tid] = 0.f; }
        if (tid == 128) z_sh[0] = 0.f;
    }

    // ---- load A tile transposed+swizzled: A_shT[k*128 + ((row + k/4)&127)] ----
    constexpr int KV = K / 4;
#pragma unroll
    for (int i = 0; i < (128 * KV) / 256; i++) {
        int v = i * 256 + tid;
        int row = v / KV;
        int k4 = v % KV;
        int gr = r0 + row;
        float4 a = (gr < NN) ? *(const float4*)(A + (size_t)gr * K + k4 * 4)
                             : make_float4(0.f, 0.f, 0.f, 0.f);
        int col = (row + k4) & 127;
        A_shT[(k4 * 4 + 0) * 128 + col] = a.x;
        A_shT[(k4 * 4 + 1) * 128 + col] = a.y;
        A_shT[(k4 * 4 + 2) * 128 + col] = a.z;
        A_shT[(k4 * 4 + 3) * 128 + col] = a.w;
    }
    __syncthreads();

    // ---- main loop ----
    unsigned long long acc[8][4];
#pragma unroll
    for (int r = 0; r < 8; r++)
#pragma unroll
        for (int jp = 0; jp < 4; jp++) acc[r][jp] = 0ull;

    for (int k0 = 0; k0 < K; k0 += 16) {
        if (k0) __syncthreads();
        {
            int wr = tid >> 4;
            int wc = (tid & 15) * 8;
            const float* wp = W + (size_t)(k0 + wr) * HID + wc;
            *(float4*)&W_sh[wr * 128 + wc]     = *(const float4*)wp;
            *(float4*)&W_sh[wr * 128 + wc + 4] = *(const float4*)(wp + 4);
        }
        __syncthreads();
#pragma unroll
        for (int kk = 0; kk < 16; kk++) {
            const int kabs = k0 + kk;
            ulonglong2 w01 = *(const ulonglong2*)&W_sh[kk * 128 + txc];
            ulonglong2 w23 = *(const ulonglong2*)&W_sh[kk * 128 + txc + 4];
            const float* arow = &A_shT[kabs * 128];
            const int coff = kabs >> 2;
#pragma unroll
            for (int r = 0; r < 8; r++) {
                float a = arow[(ty * 8 + r + coff) & 127];
                unsigned long long a2 = pack2(a);
                fma2(acc[r][0], a2, w01.x);
                fma2(acc[r][1], a2, w01.y);
                fma2(acc[r][2], a2, w23.x);
                fma2(acc[r][3], a2, w23.y);
            }
        }
    }

    // ---- epilogue ----
    float4 b0 = *(const float4*)(bias + txc);
    float4 b1 = *(const float4*)(bias + txc + 4);
    float bb[8] = {b0.x, b0.y, b0.z, b0.w, b1.x, b1.y, b1.z, b1.w};

    if (!SECOND) {
#pragma unroll
        for (int r = 0; r < 8; r++) {
            int gr = r0 + ty * 8 + r;
            if (gr >= NN) continue;
            float rs = d_rowsum[gr];
            float o[8];
#pragma unroll
            for (int jp = 0; jp < 4; jp++)
                unpack2(acc[r][jp], o[jp * 2], o[jp * 2 + 1]);
            float4 lo, hi;
            lo.x = fmaxf(o[0] + rs * bb[0], 0.f);
            lo.y = fmaxf(o[1] + rs * bb[1], 0.f);
            lo.z = fmaxf(o[2] + rs * bb[2], 0.f);
            lo.w = fmaxf(o[3] + rs * bb[3], 0.f);
            hi.x = fmaxf(o[4] + rs * bb[4], 0.f);
            hi.y = fmaxf(o[5] + rs * bb[5], 0.f);
            hi.z = fmaxf(o[6] + rs * bb[6], 0.f);
            hi.w = fmaxf(o[7] + rs * bb[7], 0.f);
            float* cp = d_h1 + (size_t)gr * HID + txc;
            *(float4*)cp       = lo;
            *(float4*)(cp + 4) = hi;
        }
    } else {
        float res[8][8];
        float sc[8];
        float ab = att_b[0];
#pragma unroll
        for (int r = 0; r < 8; r++) {
            int gr = r0 + ty * 8 + r;
            bool ok = gr < NN;
            float rs = ok ? d_rowsum[gr] : 0.f;
            float o[8];
#pragma unroll
            for (int jp = 0; jp < 4; jp++)
                unpack2(acc[r][jp], o[jp * 2], o[jp * 2 + 1]);
#pragma unroll
            for (int j = 0; j < 8; j++)
                res[r][j] = fmaxf(o[j] + rs * bb[j], 0.f);
            if (ok) {
                const float* h1p = d_h1 + (size_t)gr * HID + txc;
                float4 ha = *(const float4*)h1p;
                float4 hc = *(const float4*)(h1p + 4);
                res[r][0] += ha.x; res[r][1] += ha.y;
                res[r][2] += ha.z; res[r][3] += ha.w;
                res[r][4] += hc.x; res[r][5] += hc.y;
                res[r][6] += hc.z; res[r][7] += hc.w;
            }
            float pr = 0.f;
#pragma unroll
            for (int j = 0; j < 8; j++) pr += res[r][j] * aw_sh[txc + j];
            sc[r] = pr;
        }
        // reduce scores across the 16 tx lanes (stays within warp halves)
#pragma unroll
        for (int r = 0; r < 8; r++) {
#pragma unroll
            for (int off = 1; off < 16; off <<= 1)
                sc[r] += __shfl_xor_sync(0xFFFFFFFFu, sc[r], off);
        }
        if (tx == 0) {
#pragma unroll
            for (int r = 0; r < 8; r++) {
                int gr = r0 + ty * 8 + r;
                s_sh[ty * 8 + r] = (gr < NN) ? (sc[r] + ab) : -FLT_MAX;
            }
        }
        __syncthreads();
        // block max of scores
        {
            float v = s_sh[tid & 127];
#pragma unroll
            for (int off = 16; off; off >>= 1)
                v = fmaxf(v, __shfl_xor_sync(0xFFFFFFFFu, v, off));
            if ((tid & 31) == 0) wmax[tid >> 5] = v;
        }
        __syncthreads();
        if (tid == 0) {
            float m = wmax[0];
#pragma unroll
            for (int i = 1; i < 8; i++) m = fmaxf(m, wmax[i]);
            m_sh[0] = m;
        }
        __syncthreads();
        float mb = m_sh[0];
        float pg[8];
#pragma unroll
        for (int j = 0; j < 8; j++) pg[j] = 0.f;
        float ze = 0.f;
#pragma unroll
        for (int r = 0; r < 8; r++) {
            float e = __expf(s_sh[ty * 8 + r] - mb);
            ze += e;
#pragma unroll
            for (int j = 0; j < 8; j++) pg[j] += e * res[r][j];
        }
#pragma unroll
        for (int j = 0; j < 8; j++) atomicAdd(&g_sh[txc + j], pg[j]);
        if (tx == 0) atomicAdd(&z_sh[0], ze);
        __syncthreads();
        float* pp = d_part + (size_t)blockIdx.x * 130;
        if (tid < 128) pp[tid] = g_sh[tid];
        if (tid == 128) pp[128] = z_sh[0];
        if (tid == 129) pp[129] = mb;
    }
}

// ---------------- combine: block j<128 -> g[j]; j==128 -> Z ------------------
__global__ void k_combine() {
    __shared__ float red[256];
    __shared__ float Msh;
    int tid = threadIdx.x, j = blockIdx.x;
    float lm = -FLT_MAX;
    for (int b = tid; b < NB; b += 256)
        lm = fmaxf(lm, d_part[(size_t)b * 130 + 129]);
    red[tid] = lm;
    __syncthreads();
    for (int s = 128; s; s >>= 1) {
        if (tid < s) red[tid] = fmaxf(red[tid], red[tid + s]);
        __syncthreads();
    }
    if (tid == 0) Msh = red[0];
    __syncthreads();
    float M = Msh;
    int col = (j < 128) ? j : 128;
    float acc = 0.f;
    for (int b = tid; b < NB; b += 256) {
        float mb = d_part[(size_t)b * 130 + 129];
        acc += __expf(mb - M) * d_part[(size_t)b * 130 + col];
    }
    red[tid] = acc;
    __syncthreads();
    for (int s = 128; s; s >>= 1) {
        if (tid < s) red[tid] += red[tid + s];
        __syncthreads();
    }
    if (tid == 0) {
        if (j < 128) d_g[j] = red[0];
        else d_Z = red[0];
    }
}

// ---------------- final: out = (g/Z) @ cls_w + cls_b -------------------------
__global__ void k_final(const float* __restrict__ cls_w,
                        const float* __restrict__ cls_b,
                        float* __restrict__ out) {
    int c = threadIdx.x;
    if (c < NCLS) {
        float invZ = 1.f / d_Z;
        float acc = cls_b[c];
        for (int k = 0; k < HID; k++)
            acc += (d_g[k] * invZ) * cls_w[k * NCLS + c];
        out[c] = acc;
    }
}

// ---------------- launch ------------------------------------------------------
extern "C" void kernel_launch(void* const* d_in, const int* in_sizes, int n_in,
                              void* d_out, int out_size) {
    const float* x     = (const float*)d_in[0];
    const int*   erows = (const int*)  d_in[1];
    const int*   ecols = (const int*)  d_in[2];
    const float* evals = (const float*)d_in[3];
    const float* fc1_w = (const float*)d_in[4];
    const float* fc1_b = (const float*)d_in[5];
    const float* fc2_w = (const float*)d_in[6];
    const float* fc2_b = (const float*)d_in[7];
    const float* att_w = (const float*)d_in[8];
    const float* att_b = (const float*)d_in[9];
    const float* cls_w = (const float*)d_in[10];
    const float* cls_b = (const float*)d_in[11];
    float* out = (float*)d_out;

    float* pA1 = nullptr; float* pA2 = nullptr;
    cudaGetSymbolAddress((void**)&pA1, d_A1);
    cudaGetSymbolAddress((void**)&pA2, d_A2);

    const int extras = (128 + 128 + 128 + 8 + 1 + 1 + 2) * 4;
    const int smem1 = (IND * 128 + 16 * 128) * 4 + extras;
    const int smem2 = (HID * 128 + 16 * 128) * 4 + extras;
    cudaFuncSetAttribute(k_gemm<IND, false>,
                         cudaFuncAttributeMaxDynamicSharedMemorySize, smem1);
    cudaFuncSetAttribute(k_gemm<HID, true>,
                         cudaFuncAttributeMaxDynamicSharedMemorySize, smem2);

    k_rowptr<<<(EE + 255) / 256, 256>>>(erows);
    k_spmm64<<<(NN + 7) / 8, 256>>>(x, ecols, evals);
    k_gemm<IND, false><<<NB, 256, smem1>>>(pA1, fc1_w, fc1_b, nullptr, nullptr);
    k_spmm128<<<(NN + 7) / 8, 256>>>(ecols, evals);
    k_gemm<HID, true><<<NB, 256, smem2>>>(pA2, fc2_w, fc2_b, att_w, att_b);
    k_combine<<<129, 256>>>();
    k_final<<<1, 32>>>(cls_w, cls_b, out);
}

// round 4
// speedup vs baseline: 1.5446x; 1.0535x over previous
#include <cuda_runtime.h>
#include <cuda_fp16.h>
#include <math.h>
#include <float.h>

#define NN 100000
#define EE 3200000
#define IND 64
#define HID 128
#define NCLS 10
#define NB ((NN + 127) / 128)

// ---------------- scratch (device globals) ----------------------------------
__device__ __half d_xh[(size_t)NN * IND];    // x in fp16           [N,64]
__device__ float  d_A1[(size_t)NN * IND];    // adj @ x             [N,64]
__device__ __half d_h1h[(size_t)NN * HID];   // layer-1 out (fp16)  [N,128]
__device__ float  d_A2[(size_t)NN * HID];    // adj @ h1            [N,128]
__device__ float  d_rowsum[NN];
__device__ int    d_rowptr[NN + 1];
__device__ float  d_part[(size_t)NB * 130];  // per-block g[128], Z, m
__device__ float  d_g[HID];
__device__ float  d_Z;

// ---------------- helpers ----------------------------------------------------
__device__ __forceinline__ unsigned long long pack2(float a) {
    unsigned long long r;
    asm("mov.b64 %0, {%1, %1};" : "=l"(r) : "f"(a));
    return r;
}
__device__ __forceinline__ void fma2(unsigned long long& d,
                                     unsigned long long a, unsigned long long b) {
    asm("fma.rn.f32x2 %0, %1, %2, %0;" : "+l"(d) : "l"(a), "l"(b));
}
__device__ __forceinline__ void unpack2(unsigned long long v, float& lo, float& hi) {
    asm("mov.b64 {%0, %1}, %2;" : "=f"(lo), "=f"(hi) : "l"(v));
}

// ---------------- kernel 0: rowptr scatter + x -> fp16 -----------------------
__global__ void k_rowptr(const int* __restrict__ erows) {
    int i = blockIdx.x * blockDim.x + threadIdx.x;
    if (i >= EE) return;
    int r1 = erows[i];
    int r0 = (i == 0) ? -1 : erows[i - 1];
    for (int r = r0 + 1; r <= r1; r++) d_rowptr[r] = i;
    if (i == EE - 1)
        for (int r = r1 + 1; r <= NN; r++) d_rowptr[r] = EE;
}

__global__ void k_cvtx(const float* __restrict__ x) {
    int i = blockIdx.x * blockDim.x + threadIdx.x;
    if (i >= (NN * IND) / 4) return;
    float4 v = ((const float4*)x)[i];
    __half2 a = __floats2half2_rn(v.x, v.y);
    __half2 b = __floats2half2_rn(v.z, v.w);
    ((uint2*)d_xh)[i] = make_uint2(*(unsigned*)&a, *(unsigned*)&b);
}

// ---------------- SpMM (warp per row), 64-wide fp16 gather + rowsum ----------
__global__ void k_spmm64(const int* __restrict__ cols,
                         const float* __restrict__ vals) {
    int row = blockIdx.x * 8 + (threadIdx.x >> 5);
    if (row >= NN) return;
    int lane = threadIdx.x & 31;
    int s = d_rowptr[row], e = d_rowptr[row + 1];
    float2 acc = make_float2(0.f, 0.f);
    float vs = 0.f;
    const __half2* m2 = (const __half2*)d_xh;   // 32 half2 per row
    int i = s;
    if ((i & 1) && i < e) {
        float v = __ldg(vals + i);
        int   c = __ldg(cols + i);
        float2 xv = __half22float2(m2[(size_t)c * 32 + lane]);
        acc.x += v * xv.x; acc.y += v * xv.y; vs += v;
        i++;
    }
    for (; i + 2 <= e; i += 2) {
        float2 v2 = *(const float2*)(vals + i);
        int2   c2 = *(const int2*)(cols + i);
        float2 xa = __half22float2(m2[(size_t)c2.x * 32 + lane]);
        float2 xb = __half22float2(m2[(size_t)c2.y * 32 + lane]);
        acc.x += v2.x * xa.x; acc.y += v2.x * xa.y;
        acc.x += v2.y * xb.x; acc.y += v2.y * xb.y;
        vs += v2.x + v2.y;
    }
    if (i < e) {
        float v = __ldg(vals + i);
        int   c = __ldg(cols + i);
        float2 xv = __half22float2(m2[(size_t)c * 32 + lane]);
        acc.x += v * xv.x; acc.y += v * xv.y; vs += v;
    }
    ((float2*)d_A1)[(size_t)row * 32 + lane] = acc;
    if (lane == 0) d_rowsum[row] = vs;
}

// ---------------- SpMM (warp per row), 128-wide fp16 gather ------------------
__device__ __forceinline__ void gather128(const uint2* __restrict__ m,
                                          int c, int lane, float v,
                                          float4& acc) {
    uint2 raw = m[(size_t)c * 32 + lane];
    float2 f01 = __half22float2(*(__half2*)&raw.x);
    float2 f23 = __half22float2(*(__half2*)&raw.y);
    acc.x += v * f01.x; acc.y += v * f01.y;
    acc.z += v * f23.x; acc.w += v * f23.y;
}

__global__ void k_spmm128(const int* __restrict__ cols,
                          const float* __restrict__ vals) {
    int row = blockIdx.x * 8 + (threadIdx.x >> 5);
    if (row >= NN) return;
    int lane = threadIdx.x & 31;
    int s = d_rowptr[row], e = d_rowptr[row + 1];
    float4 acc = make_float4(0.f, 0.f, 0.f, 0.f);
    const uint2* m = (const uint2*)d_h1h;   // 32 uint2 (4 halfs) per row
    int i = s;
    if ((i & 1) && i < e) {
        float v = __ldg(vals + i);
        int   c = __ldg(cols + i);
        gather128(m, c, lane, v, acc);
        i++;
    }
    for (; i + 2 <= e; i += 2) {
        float2 v2 = *(const float2*)(vals + i);
        int2   c2 = *(const int2*)(cols + i);
        gather128(m, c2.x, lane, v2.x, acc);
        gather128(m, c2.y, lane, v2.y, acc);
    }
    if (i < e) {
        float v = __ldg(vals + i);
        int   c = __ldg(cols + i);
        gather128(m, c, lane, v, acc);
    }
    ((float4*)d_A2)[(size_t)row * 32 + lane] = acc;
}

// ---------------- GEMM: 128x128 tile, f32x2, swizzled transposed A -----------
//   !SECOND: d_h1h = fp16(relu(acc + rowsum*b))
//    SECOND: h = h1 + relu(acc + rowsum*b); per-block softmax-pool partials.
template <int K, bool SECOND>
__global__ void __launch_bounds__(256, 2)
k_gemm(const float* __restrict__ A,
       const float* __restrict__ W,
       const float* __restrict__ bias,
       const float* __restrict__ att_w,
       const float* __restrict__ att_b) {
    extern __shared__ float sm[];
    float* A_shT = sm;                    // K*128, swizzled
    float* W_sh  = sm + K * 128;          // 16*128
    float* aw_sh = W_sh + 16 * 128;       // 128
    float* s_sh  = aw_sh + 128;           // 128
    float* g_sh  = s_sh + 128;            // 128
    float* wmax  = g_sh + 128;            // 8
    float* m_sh  = wmax + 8;              // 1
    float* z_sh  = m_sh + 1;              // 1

    const int tid = threadIdx.x;
    const int r0 = blockIdx.x * 128;
    const int tx = tid & 15, ty = tid >> 4;
    const int txc = tx * 8;

    if (SECOND) {
        if (tid < 128) { aw_sh[tid] = att_w[tid]; g_sh[tid] = 0.f; }
        if (tid == 128) z_sh[0] = 0.f;
    }

    // ---- load A tile transposed+swizzled ----
    constexpr int KV = K / 4;
#pragma unroll
    for (int i = 0; i < (128 * KV) / 256; i++) {
        int v = i * 256 + tid;
        int row = v / KV;
        int k4 = v % KV;
        int gr = r0 + row;
        float4 a = (gr < NN) ? *(const float4*)(A + (size_t)gr * K + k4 * 4)
                             : make_float4(0.f, 0.f, 0.f, 0.f);
        int col = (row + k4) & 127;
        A_shT[(k4 * 4 + 0) * 128 + col] = a.x;
        A_shT[(k4 * 4 + 1) * 128 + col] = a.y;
        A_shT[(k4 * 4 + 2) * 128 + col] = a.z;
        A_shT[(k4 * 4 + 3) * 128 + col] = a.w;
    }
    __syncthreads();

    // ---- main loop ----
    unsigned long long acc[8][4];
#pragma unroll
    for (int r = 0; r < 8; r++)
#pragma unroll
        for (int jp = 0; jp < 4; jp++) acc[r][jp] = 0ull;

    for (int k0 = 0; k0 < K; k0 += 16) {
        if (k0) __syncthreads();
        {
            int wr = tid >> 4;
            int wc = (tid & 15) * 8;
            const float* wp = W + (size_t)(k0 + wr) * HID + wc;
            *(float4*)&W_sh[wr * 128 + wc]     = *(const float4*)wp;
            *(float4*)&W_sh[wr * 128 + wc + 4] = *(const float4*)(wp + 4);
        }
        __syncthreads();
#pragma unroll
        for (int kk = 0; kk < 16; kk++) {
            const int kabs = k0 + kk;
            ulonglong2 w01 = *(const ulonglong2*)&W_sh[kk * 128 + txc];
            ulonglong2 w23 = *(const ulonglong2*)&W_sh[kk * 128 + txc + 4];
            const float* arow = &A_shT[kabs * 128];
            const int coff = kabs >> 2;
#pragma unroll
            for (int r = 0; r < 8; r++) {
                float a = arow[(ty * 8 + r + coff) & 127];
                unsigned long long a2 = pack2(a);
                fma2(acc[r][0], a2, w01.x);
                fma2(acc[r][1], a2, w01.y);
                fma2(acc[r][2], a2, w23.x);
                fma2(acc[r][3], a2, w23.y);
            }
        }
    }

    // ---- epilogue ----
    float4 b0 = *(const float4*)(bias + txc);
    float4 b1 = *(const float4*)(bias + txc + 4);
    float bb[8] = {b0.x, b0.y, b0.z, b0.w, b1.x, b1.y, b1.z, b1.w};

    if (!SECOND) {
#pragma unroll
        for (int r = 0; r < 8; r++) {
            int gr = r0 + ty * 8 + r;
            if (gr >= NN) continue;
            float rs = d_rowsum[gr];
            float o[8];
#pragma unroll
            for (int jp = 0; jp < 4; jp++)
                unpack2(acc[r][jp], o[jp * 2], o[jp * 2 + 1]);
            float res[8];
#pragma unroll
            for (int j = 0; j < 8; j++) res[j] = fmaxf(o[j] + rs * bb[j], 0.f);
            __half2 h0 = __floats2half2_rn(res[0], res[1]);
            __half2 h1 = __floats2half2_rn(res[2], res[3]);
            __half2 h2 = __floats2half2_rn(res[4], res[5]);
            __half2 h3 = __floats2half2_rn(res[6], res[7]);
            uint4 st = make_uint4(*(unsigned*)&h0, *(unsigned*)&h1,
                                  *(unsigned*)&h2, *(unsigned*)&h3);
            *(uint4*)(d_h1h + (size_t)gr * HID + txc) = st;
        }
    } else {
        float res[8][8];
        float sc[8];
        float ab = att_b[0];
#pragma unroll
        for (int r = 0; r < 8; r++) {
            int gr = r0 + ty * 8 + r;
            bool ok = gr < NN;
            float rs = ok ? d_rowsum[gr] : 0.f;
            float o[8];
#pragma unroll
            for (int jp = 0; jp < 4; jp++)
                unpack2(acc[r][jp], o[jp * 2], o[jp * 2 + 1]);
#pragma unroll
            for (int j = 0; j < 8; j++)
                res[r][j] = fmaxf(o[j] + rs * bb[j], 0.f);
            if (ok) {
                uint4 raw = *(const uint4*)(d_h1h + (size_t)gr * HID + txc);
                float2 f0 = __half22float2(*(__half2*)&raw.x);
                float2 f1 = __half22float2(*(__half2*)&raw.y);
                float2 f2 = __half22float2(*(__half2*)&raw.z);
                float2 f3 = __half22float2(*(__half2*)&raw.w);
                res[r][0] += f0.x; res[r][1] += f0.y;
                res[r][2] += f1.x; res[r][3] += f1.y;
                res[r][4] += f2.x; res[r][5] += f2.y;
                res[r][6] += f3.x; res[r][7] += f3.y;
            }
            float pr = 0.f;
#pragma unroll
            for (int j = 0; j < 8; j++) pr += res[r][j] * aw_sh[txc + j];
            sc[r] = pr;
        }
#pragma unroll
        for (int r = 0; r < 8; r++) {
#pragma unroll
            for (int off = 1; off < 16; off <<= 1)
                sc[r] += __shfl_xor_sync(0xFFFFFFFFu, sc[r], off);
        }
        if (tx == 0) {
#pragma unroll
            for (int r = 0; r < 8; r++) {
                int gr = r0 + ty * 8 + r;
                s_sh[ty * 8 + r] = (gr < NN) ? (sc[r] + ab) : -FLT_MAX;
            }
        }
        __syncthreads();
        {
            float v = s_sh[tid & 127];
#pragma unroll
            for (int off = 16; off; off >>= 1)
                v = fmaxf(v, __shfl_xor_sync(0xFFFFFFFFu, v, off));
            if ((tid & 31) == 0) wmax[tid >> 5] = v;
        }
        __syncthreads();
        if (tid == 0) {
            float m = wmax[0];
#pragma unroll
            for (int i = 1; i < 8; i++) m = fmaxf(m, wmax[i]);
            m_sh[0] = m;
        }
        __syncthreads();
        float mb = m_sh[0];
        float pg[8];
#pragma unroll
        for (int j = 0; j < 8; j++) pg[j] = 0.f;
        float ze = 0.f;
#pragma unroll
        for (int r = 0; r < 8; r++) {
            float e = __expf(s_sh[ty * 8 + r] - mb);
            ze += e;
#pragma unroll
            for (int j = 0; j < 8; j++) pg[j] += e * res[r][j];
        }
#pragma unroll
        for (int j = 0; j < 8; j++) atomicAdd(&g_sh[txc + j], pg[j]);
        if (tx == 0) atomicAdd(&z_sh[0], ze);
        __syncthreads();
        float* pp = d_part + (size_t)blockIdx.x * 130;
        if (tid < 128) pp[tid] = g_sh[tid];
        if (tid == 128) pp[128] = z_sh[0];
        if (tid == 129) pp[129] = mb;
    }
}

// ---------------- combine: block j<128 -> g[j]; j==128 -> Z ------------------
__global__ void k_combine() {
    __shared__ float red[256];
    __shared__ float Msh;
    int tid = threadIdx.x, j = blockIdx.x;
    float lm = -FLT_MAX;
    for (int b = tid; b < NB; b += 256)
        lm = fmaxf(lm, d_part[(size_t)b * 130 + 129]);
    red[tid] = lm;
    __syncthreads();
    for (int s = 128; s; s >>= 1) {
        if (tid < s) red[tid] = fmaxf(red[tid], red[tid + s]);
        __syncthreads();
    }
    if (tid == 0) Msh = red[0];
    __syncthreads();
    float M = Msh;
    int col = (j < 128) ? j : 128;
    float acc = 0.f;
    for (int b = tid; b < NB; b += 256) {
        float mb = d_part[(size_t)b * 130 + 129];
        acc += __expf(mb - M) * d_part[(size_t)b * 130 + col];
    }
    red[tid] = acc;
    __syncthreads();
    for (int s = 128; s; s >>= 1) {
        if (tid < s) red[tid] += red[tid + s];
        __syncthreads();
    }
    if (tid == 0) {
        if (j < 128) d_g[j] = red[0];
        else d_Z = red[0];
    }
}

// ---------------- final: out = (g/Z) @ cls_w + cls_b -------------------------
__global__ void k_final(const float* __restrict__ cls_w,
                        const float* __restrict__ cls_b,
                        float* __restrict__ out) {
    int c = threadIdx.x;
    if (c < NCLS) {
        float invZ = 1.f / d_Z;
        float acc = cls_b[c];
        for (int k = 0; k < HID; k++)
            acc += (d_g[k] * invZ) * cls_w[k * NCLS + c];
        out[c] = acc;
    }
}

// ---------------- launch ------------------------------------------------------
extern "C" void kernel_launch(void* const* d_in, const int* in_sizes, int n_in,
                              void* d_out, int out_size) {
    const float* x     = (const float*)d_in[0];
    const int*   erows = (const int*)  d_in[1];
    const int*   ecols = (const int*)  d_in[2];
    const float* evals = (const float*)d_in[3];
    const float* fc1_w = (const float*)d_in[4];
    const float* fc1_b = (const float*)d_in[5];
    const float* fc2_w = (const float*)d_in[6];
    const float* fc2_b = (const float*)d_in[7];
    const float* att_w = (const float*)d_in[8];
    const float* att_b = (const float*)d_in[9];
    const float* cls_w = (const float*)d_in[10];
    const float* cls_b = (const float*)d_in[11];
    float* out = (float*)d_out;

    float* pA1 = nullptr; float* pA2 = nullptr;
    cudaGetSymbolAddress((void**)&pA1, d_A1);
    cudaGetSymbolAddress((void**)&pA2, d_A2);

    const int extras = (128 + 128 + 128 + 8 + 1 + 1 + 2) * 4;
    const int smem1 = (IND * 128 + 16 * 128) * 4 + extras;
    const int smem2 = (HID * 128 + 16 * 128) * 4 + extras;
    cudaFuncSetAttribute(k_gemm<IND, false>,
                         cudaFuncAttributeMaxDynamicSharedMemorySize, smem1);
    cudaFuncSetAttribute(k_gemm<HID, true>,
                         cudaFuncAttributeMaxDynamicSharedMemorySize, smem2);

    k_rowptr<<<(EE + 255) / 256, 256>>>(erows);
    k_cvtx<<<((NN * IND / 4) + 255) / 256, 256>>>(x);
    k_spmm64<<<(NN + 7) / 8, 256>>>(ecols, evals);
    k_gemm<IND, false><<<NB, 256, smem1>>>(pA1, fc1_w, fc1_b, nullptr, nullptr);
    k_spmm128<<<(NN + 7) / 8, 256>>>(ecols, evals);
    k_gemm<HID, true><<<NB, 256, smem2>>>(pA2, fc2_w, fc2_b, att_w, att_b);
    k_combine<<<129, 256>>>();
    k_final<<<1, 32>>>(cls_w, cls_b, out);
}

// round 5
// speedup vs baseline: 2.2359x; 1.4476x over previous
#include <cuda_runtime.h>
#include <cuda_fp16.h>
#include <math.h>
#include <float.h>

#define NN 100000
#define EE 3200000
#define IND 64
#define HID 128
#define NCLS 10
#define NB ((NN + 127) / 128)

// ---------------- scratch (device globals) ----------------------------------
__device__ __align__(16) __half d_xh [(size_t)NN * IND];   // x fp16
__device__ __align__(16) __half d_A1h[(size_t)NN * IND];   // adj@x fp16
__device__ __align__(16) __half d_h1h[(size_t)NN * HID];   // h1 fp16
__device__ __align__(16) __half d_A2h[(size_t)NN * HID];   // adj@h1 fp16
__device__ __align__(16) __half d_w1t[HID * IND];          // fc1_w^T [n=128][k=64]
__device__ __align__(16) __half d_w2t[HID * HID];          // fc2_w^T [n=128][k=128]
__device__ float d_rowsum[NN];
__device__ int   d_rowptr[NN + 1];
__device__ float d_part[(size_t)NB * 130];                 // g[128], Z, m per block
__device__ float d_g[HID];
__device__ float d_Z;

// ---------------- mma helpers -------------------------------------------------
__device__ __forceinline__ void ldsm4(unsigned& r0, unsigned& r1,
                                      unsigned& r2, unsigned& r3, unsigned addr) {
    asm volatile("ldmatrix.sync.aligned.m8n8.x4.shared.b16 {%0,%1,%2,%3}, [%4];"
                 : "=r"(r0), "=r"(r1), "=r"(r2), "=r"(r3) : "r"(addr));
}
__device__ __forceinline__ void mma16816(float* c,
                                         unsigned a0, unsigned a1, unsigned a2, unsigned a3,
                                         unsigned b0, unsigned b1) {
    asm volatile("mma.sync.aligned.m16n8k16.row.col.f32.f16.f16.f32 "
                 "{%0,%1,%2,%3}, {%4,%5,%6,%7}, {%8,%9}, {%0,%1,%2,%3};"
                 : "+f"(c[0]), "+f"(c[1]), "+f"(c[2]), "+f"(c[3])
                 : "r"(a0), "r"(a1), "r"(a2), "r"(a3), "r"(b0), "r"(b1));
}

// ---------------- kernel 0: rowptr scatter + conversions ----------------------
__global__ void k_rowptr(const int* __restrict__ erows) {
    int i = blockIdx.x * blockDim.x + threadIdx.x;
    if (i >= EE) return;
    int r1 = erows[i];
    int r0 = (i == 0) ? -1 : erows[i - 1];
    for (int r = r0 + 1; r <= r1; r++) d_rowptr[r] = i;
    if (i == EE - 1)
        for (int r = r1 + 1; r <= NN; r++) d_rowptr[r] = EE;
}

__global__ void k_cvtx(const float* __restrict__ x) {
    int i = blockIdx.x * blockDim.x + threadIdx.x;
    if (i >= (NN * IND) / 4) return;
    float4 v = ((const float4*)x)[i];
    __half2 a = __floats2half2_rn(v.x, v.y);
    __half2 b = __floats2half2_rn(v.z, v.w);
    ((uint2*)d_xh)[i] = make_uint2(*(unsigned*)&a, *(unsigned*)&b);
}

// Wt[n][k] = W[k][n], fp16
__global__ void k_cvtw(const float* __restrict__ W, __half* __restrict__ Wt, int Kd) {
    int idx = blockIdx.x * blockDim.x + threadIdx.x;
    if (idx >= 128 * Kd) return;
    int n = idx / Kd, k = idx % Kd;
    Wt[idx] = __float2half(W[k * 128 + n]);
}

// ---------------- SpMM (warp per row), 64-wide fp16 gather + rowsum ----------
__global__ void k_spmm64(const int* __restrict__ cols,
                         const float* __restrict__ vals) {
    int row = blockIdx.x * 8 + (threadIdx.x >> 5);
    if (row >= NN) return;
    int lane = threadIdx.x & 31;
    int s = d_rowptr[row], e = d_rowptr[row + 1];
    float2 acc = make_float2(0.f, 0.f);
    float vs = 0.f;
    const __half2* m2 = (const __half2*)d_xh;
    int i = s;
    if ((i & 1) && i < e) {
        float v = __ldg(vals + i);
        int   c = __ldg(cols + i);
        float2 xv = __half22float2(m2[(size_t)c * 32 + lane]);
        acc.x += v * xv.x; acc.y += v * xv.y; vs += v;
        i++;
    }
    for (; i + 2 <= e; i += 2) {
        float2 v2 = *(const float2*)(vals + i);
        int2   c2 = *(const int2*)(cols + i);
        float2 xa = __half22float2(m2[(size_t)c2.x * 32 + lane]);
        float2 xb = __half22float2(m2[(size_t)c2.y * 32 + lane]);
        acc.x += v2.x * xa.x; acc.y += v2.x * xa.y;
        acc.x += v2.y * xb.x; acc.y += v2.y * xb.y;
        vs += v2.x + v2.y;
    }
    if (i < e) {
        float v = __ldg(vals + i);
        int   c = __ldg(cols + i);
        float2 xv = __half22float2(m2[(size_t)c * 32 + lane]);
        acc.x += v * xv.x; acc.y += v * xv.y; vs += v;
    }
    __half2 st = __floats2half2_rn(acc.x, acc.y);
    ((__half2*)d_A1h)[(size_t)row * 32 + lane] = st;
    if (lane == 0) d_rowsum[row] = vs;
}

// ---------------- SpMM (warp per row), 128-wide fp16 gather ------------------
__device__ __forceinline__ void gather128(const uint2* __restrict__ m,
                                          int c, int lane, float v, float4& acc) {
    uint2 raw = m[(size_t)c * 32 + lane];
    float2 f01 = __half22float2(*(__half2*)&raw.x);
    float2 f23 = __half22float2(*(__half2*)&raw.y);
    acc.x += v * f01.x; acc.y += v * f01.y;
    acc.z += v * f23.x; acc.w += v * f23.y;
}

__global__ void k_spmm128(const int* __restrict__ cols,
                          const float* __restrict__ vals) {
    int row = blockIdx.x * 8 + (threadIdx.x >> 5);
    if (row >= NN) return;
    int lane = threadIdx.x & 31;
    int s = d_rowptr[row], e = d_rowptr[row + 1];
    float4 acc = make_float4(0.f, 0.f, 0.f, 0.f);
    const uint2* m = (const uint2*)d_h1h;
    int i = s;
    if ((i & 1) && i < e) {
        float v = __ldg(vals + i);
        int   c = __ldg(cols + i);
        gather128(m, c, lane, v, acc);
        i++;
    }
    for (; i + 2 <= e; i += 2) {
        float2 v2 = *(const float2*)(vals + i);
        int2   c2 = *(const int2*)(cols + i);
        gather128(m, c2.x, lane, v2.x, acc);
        gather128(m, c2.y, lane, v2.y, acc);
    }
    if (i < e) {
        float v = __ldg(vals + i);
        int   c = __ldg(cols + i);
        gather128(m, c, lane, v, acc);
    }
    __half2 h01 = __floats2half2_rn(acc.x, acc.y);
    __half2 h23 = __floats2half2_rn(acc.z, acc.w);
    ((uint2*)d_A2h)[(size_t)row * 32 + lane] =
        make_uint2(*(unsigned*)&h01, *(unsigned*)&h23);
}

// ---------------- tensor-core GEMM: 128 rows x 128 cols per block ------------
// warp w: rows w*16..w*16+15, all 128 cols (16 n8 tiles), K in k16 chunks.
//   !SECOND: d_h1h = fp16(relu(acc + rowsum*b))
//    SECOND: h = h1 + relu(acc + rowsum*b); block softmax-pool partials.
template <int K, bool SECOND>
__global__ void __launch_bounds__(256, 2)
k_gemm_mma(const __half* __restrict__ Ag, const __half* __restrict__ Wt,
           const float* __restrict__ bias,
           const float* __restrict__ att_w, const float* __restrict__ att_b) {
    extern __shared__ __align__(16) char smraw[];
    __half* A_sh = (__half*)smraw;          // 128*K halfs, swizzled
    __half* W_sh = A_sh + 128 * K;          // 128*K halfs, swizzled
    float* bias_sh = (float*)(W_sh + 128 * K);
    float* aw_sh = bias_sh + 128;
    float* s_sh  = aw_sh + 128;
    float* g_sh  = s_sh + 128;
    float* wmax  = g_sh + 128;              // 8
    float* m_sh  = wmax + 8;
    float* z_sh  = m_sh + 1;

    const int tid = threadIdx.x;
    const int r0 = blockIdx.x * 128;
    const int w = tid >> 5, lane = tid & 31;
    const int q = lane & 3, g8 = lane >> 2;

    if (tid < 128) {
        bias_sh[tid] = bias[tid];
        if (SECOND) { aw_sh[tid] = att_w[tid]; g_sh[tid] = 0.f; }
    }
    if (SECOND && tid == 128) z_sh[0] = 0.f;

    constexpr int GPR = K / 8;  // 16-byte groups per row
    {
        const uint4* src = (const uint4*)Ag;
#pragma unroll
        for (int i = 0; i < 128 * GPR / 256; i++) {
            int idx = i * 256 + tid;
            int row = idx / GPR, g = idx % GPR;
            int gr = r0 + row;
            uint4 v = make_uint4(0, 0, 0, 0);
            if (gr < NN) v = src[(size_t)gr * GPR + g];
            *(uint4*)&A_sh[row * K + ((g ^ (row & 7)) << 3)] = v;
        }
        const uint4* ws = (const uint4*)Wt;
#pragma unroll
        for (int i = 0; i < 128 * GPR / 256; i++) {
            int idx = i * 256 + tid;
            int row = idx / GPR, g = idx % GPR;
            *(uint4*)&W_sh[row * K + ((g ^ (row & 7)) << 3)] = ws[idx];
        }
    }
    __syncthreads();

    unsigned aBase = (unsigned)__cvta_generic_to_shared(A_sh);
    unsigned wBase = (unsigned)__cvta_generic_to_shared(W_sh);

    const int rowA   = w * 16 + ((lane >> 3) & 1) * 8 + (lane & 7);
    const int khalfA = lane >> 4;
    const int rowBoff = ((lane >> 4) & 1) * 8 + (lane & 7);
    const int khalfB  = (lane >> 3) & 1;
    const int l7 = lane & 7;

    float acc[16][4];
#pragma unroll
    for (int t = 0; t < 16; t++)
#pragma unroll
        for (int p = 0; p < 4; p++) acc[t][p] = 0.f;

#pragma unroll
    for (int kc = 0; kc < K; kc += 16) {
        unsigned a0, a1, a2, a3;
        int grpA = (kc >> 3) + khalfA;
        ldsm4(a0, a1, a2, a3,
              aBase + (unsigned)(rowA * K + ((grpA ^ (rowA & 7)) << 3)) * 2u);
        int grpB = (kc >> 3) + khalfB;
#pragma unroll
        for (int jj = 0; jj < 8; jj++) {
            int rowB = jj * 16 + rowBoff;
            unsigned b0, b1, b2, b3;
            ldsm4(b0, b1, b2, b3,
                  wBase + (unsigned)(rowB * K + ((grpB ^ l7) << 3)) * 2u);
            mma16816(acc[2 * jj],     a0, a1, a2, a3, b0, b1);
            mma16816(acc[2 * jj + 1], a0, a1, a2, a3, b2, b3);
        }
    }

    // ---- epilogue (fragment layout: rows lr0=w*16+g8, lr1=lr0+8;
    //      tile t covers cols 8t; thread owns cols 8t+2q, 8t+2q+1) ----
    const int lr0 = w * 16 + g8, lr1 = lr0 + 8;
    const int gr0 = r0 + lr0, gr1 = r0 + lr1;
    const float rs0 = (gr0 < NN) ? d_rowsum[gr0] : 0.f;
    const float rs1 = (gr1 < NN) ? d_rowsum[gr1] : 0.f;

    // in-place: acc[t][p]   <- res row0 col (8t+2q+p)
    //           acc[t][2+p] <- res row1 col (8t+2q+p)
#pragma unroll
    for (int t = 0; t < 16; t++) {
#pragma unroll
        for (int p = 0; p < 2; p++) {
            float b = bias_sh[8 * t + 2 * q + p];
            acc[t][p]     = fmaxf(acc[t][p]     + rs0 * b, 0.f);
            acc[t][2 + p] = fmaxf(acc[t][2 + p] + rs1 * b, 0.f);
        }
    }

    if (!SECOND) {
#pragma unroll
        for (int t = 0; t < 16; t++) {
            int col = 8 * t + 2 * q;
            if (gr0 < NN) {
                __half2 h = __floats2half2_rn(acc[t][0], acc[t][1]);
                *(__half2*)&d_h1h[(size_t)gr0 * HID + col] = h;
            }
            if (gr1 < NN) {
                __half2 h = __floats2half2_rn(acc[t][2], acc[t][3]);
                *(__half2*)&d_h1h[(size_t)gr1 * HID + col] = h;
            }
        }
        return;
    } else {
        float sc0 = 0.f, sc1 = 0.f;
#pragma unroll
        for (int t = 0; t < 16; t++) {
            int col = 8 * t + 2 * q;
            if (gr0 < NN) {
                float2 f = __half22float2(*(const __half2*)&d_h1h[(size_t)gr0 * HID + col]);
                acc[t][0] += f.x; acc[t][1] += f.y;
            }
            if (gr1 < NN) {
                float2 f = __half22float2(*(const __half2*)&d_h1h[(size_t)gr1 * HID + col]);
                acc[t][2] += f.x; acc[t][3] += f.y;
            }
            float aw0 = aw_sh[col], aw1 = aw_sh[col + 1];
            sc0 += acc[t][0] * aw0 + acc[t][1] * aw1;
            sc1 += acc[t][2] * aw0 + acc[t][3] * aw1;
        }
        sc0 += __shfl_xor_sync(0xFFFFFFFFu, sc0, 1);
        sc0 += __shfl_xor_sync(0xFFFFFFFFu, sc0, 2);
        sc1 += __shfl_xor_sync(0xFFFFFFFFu, sc1, 1);
        sc1 += __shfl_xor_sync(0xFFFFFFFFu, sc1, 2);
        float ab = att_b[0];
        if (q == 0) {
            s_sh[lr0] = (gr0 < NN) ? (sc0 + ab) : -FLT_MAX;
            s_sh[lr1] = (gr1 < NN) ? (sc1 + ab) : -FLT_MAX;
        }
        __syncthreads();
        {
            float v = s_sh[tid & 127];
#pragma unroll
            for (int off = 16; off; off >>= 1)
                v = fmaxf(v, __shfl_xor_sync(0xFFFFFFFFu, v, off));
            if (lane == 0) wmax[w] = v;
        }
        __syncthreads();
        if (tid == 0) {
            float m = wmax[0];
#pragma unroll
            for (int i = 1; i < 8; i++) m = fmaxf(m, wmax[i]);
            m_sh[0] = m;
        }
        __syncthreads();
        const float mb = m_sh[0];
        const float e0 = __expf(s_sh[lr0] - mb);
        const float e1 = __expf(s_sh[lr1] - mb);
        // pg in-place into acc[t][0..1]
#pragma unroll
        for (int t = 0; t < 16; t++) {
            acc[t][0] = e0 * acc[t][0] + e1 * acc[t][2];
            acc[t][1] = e0 * acc[t][1] + e1 * acc[t][3];
        }
#pragma unroll
        for (int off = 4; off <= 16; off <<= 1) {
#pragma unroll
            for (int t = 0; t < 16; t++) {
                acc[t][0] += __shfl_xor_sync(0xFFFFFFFFu, acc[t][0], off);
                acc[t][1] += __shfl_xor_sync(0xFFFFFFFFu, acc[t][1], off);
            }
        }
        if (lane < 4) {
#pragma unroll
            for (int t = 0; t < 16; t++) {
                atomicAdd(&g_sh[8 * t + 2 * lane],     acc[t][0]);
                atomicAdd(&g_sh[8 * t + 2 * lane + 1], acc[t][1]);
            }
        }
        float ze = (q == 0) ? (e0 + e1) : 0.f;
        ze += __shfl_xor_sync(0xFFFFFFFFu, ze, 4);
        ze += __shfl_xor_sync(0xFFFFFFFFu, ze, 8);
        ze += __shfl_xor_sync(0xFFFFFFFFu, ze, 16);
        if (lane == 0) atomicAdd(z_sh, ze);
        __syncthreads();
        float* pp = d_part + (size_t)blockIdx.x * 130;
        if (tid < 128) pp[tid] = g_sh[tid];
        if (tid == 128) pp[128] = z_sh[0];
        if (tid == 129) pp[129] = m_sh[0];
    }
}

// ---------------- combine: block j<128 -> g[j]; j==128 -> Z ------------------
__global__ void k_combine() {
    __shared__ float red[256];
    __shared__ float Msh;
    int tid = threadIdx.x, j = blockIdx.x;
    float lm = -FLT_MAX;
    for (int b = tid; b < NB; b += 256)
        lm = fmaxf(lm, d_part[(size_t)b * 130 + 129]);
    red[tid] = lm;
    __syncthreads();
    for (int s = 128; s; s >>= 1) {
        if (tid < s) red[tid] = fmaxf(red[tid], red[tid + s]);
        __syncthreads();
    }
    if (tid == 0) Msh = red[0];
    __syncthreads();
    float M = Msh;
    int col = (j < 128) ? j : 128;
    float acc = 0.f;
    for (int b = tid; b < NB; b += 256) {
        float mb = d_part[(size_t)b * 130 + 129];
        acc += __expf(mb - M) * d_part[(size_t)b * 130 + col];
    }
    red[tid] = acc;
    __syncthreads();
    for (int s = 128; s; s >>= 1) {
        if (tid < s) red[tid] += red[tid + s];
        __syncthreads();
    }
    if (tid == 0) {
        if (j < 128) d_g[j] = red[0];
        else d_Z = red[0];
    }
}

// ---------------- final: out = (g/Z) @ cls_w + cls_b -------------------------
__global__ void k_final(const float* __restrict__ cls_w,
                        const float* __restrict__ cls_b,
                        float* __restrict__ out) {
    int c = threadIdx.x;
    if (c < NCLS) {
        float invZ = 1.f / d_Z;
        float acc = cls_b[c];
        for (int k = 0; k < HID; k++)
            acc += (d_g[k] * invZ) * cls_w[k * NCLS + c];
        out[c] = acc;
    }
}

// ---------------- launch ------------------------------------------------------
extern "C" void kernel_launch(void* const* d_in, const int* in_sizes, int n_in,
                              void* d_out, int out_size) {
    const float* x     = (const float*)d_in[0];
    const int*   erows = (const int*)  d_in[1];
    const int*   ecols = (const int*)  d_in[2];
    const float* evals = (const float*)d_in[3];
    const float* fc1_w = (const float*)d_in[4];
    const float* fc1_b = (const float*)d_in[5];
    const float* fc2_w = (const float*)d_in[6];
    const float* fc2_b = (const float*)d_in[7];
    const float* att_w = (const float*)d_in[8];
    const float* att_b = (const float*)d_in[9];
    const float* cls_w = (const float*)d_in[10];
    const float* cls_b = (const float*)d_in[11];
    float* out = (float*)d_out;

    __half* pA1 = nullptr; __half* pA2 = nullptr;
    __half* pW1 = nullptr; __half* pW2 = nullptr;
    cudaGetSymbolAddress((void**)&pA1, d_A1h);
    cudaGetSymbolAddress((void**)&pA2, d_A2h);
    cudaGetSymbolAddress((void**)&pW1, d_w1t);
    cudaGetSymbolAddress((void**)&pW2, d_w2t);

    const int extras = (128 * 4 + 8 + 2) * 4;
    const int smem1 = 128 * IND * 2 * 2 + extras;
    const int smem2 = 128 * HID * 2 * 2 + extras;
    cudaFuncSetAttribute(k_gemm_mma<IND, false>,
                         cudaFuncAttributeMaxDynamicSharedMemorySize, smem1);
    cudaFuncSetAttribute(k_gemm_mma<HID, true>,
                         cudaFuncAttributeMaxDynamicSharedMemorySize, smem2);

    k_rowptr<<<(EE + 255) / 256, 256>>>(erows);
    k_cvtx<<<((NN * IND / 4) + 255) / 256, 256>>>(x);
    k_cvtw<<<(128 * IND + 255) / 256, 256>>>(fc1_w, pW1, IND);
    k_cvtw<<<(128 * HID + 255) / 256, 256>>>(fc2_w, pW2, HID);
    k_spmm64<<<(NN + 7) / 8, 256>>>(ecols, evals);
    k_gemm_mma<IND, false><<<NB, 256, smem1>>>(pA1, pW1, fc1_b, nullptr, nullptr);
    k_spmm128<<<(NN + 7) / 8, 256>>>(ecols, evals);
    k_gemm_mma<HID, true><<<NB, 256, smem2>>>(pA2, pW2, fc2_b, att_w, att_b);
    k_combine<<<129, 256>>>();
    k_final<<<1, 32>>>(cls_w, cls_b, out);
}

// round 6
// speedup vs baseline: 2.5645x; 1.1470x over previous
#include <cuda_runtime.h>
#include <cuda_fp16.h>
#include <math.h>
#include <float.h>

#define NN 100000
#define EE 3200000
#define IND 64
#define HID 128
#define NCLS 10
#define NB ((NN + 127) / 128)

// prologue block ranges
#define PB1 ((EE + 255) / 256)                 // edge scatter+pack: 12500
#define PB2 ((NN * IND / 4 + 255) / 256)       // cvtx: 6250
#define PB3 ((128 * (IND + HID) + 255) / 256)  // cvtw: 96

// ---------------- scratch (device globals) ----------------------------------
__device__ __align__(16) __half d_xh [(size_t)NN * IND];   // x fp16
__device__ __align__(16) __half d_A1h[(size_t)NN * IND];   // adj@x fp16
__device__ __align__(16) __half d_h1h[(size_t)NN * HID];   // h1 fp16
__device__ __align__(16) __half d_A2h[(size_t)NN * HID];   // adj@h1 fp16
__device__ __align__(16) __half d_w1t[HID * IND];          // fc1_w^T
__device__ __align__(16) __half d_w2t[HID * HID];          // fc2_w^T
__device__ __align__(16) int2  d_epack[EE];                // {col, val bits}
__device__ float d_rowsum[NN];
__device__ int   d_rowptr[NN + 1];
__device__ float d_part[(size_t)NB * 130];
__device__ float d_g[HID];
__device__ float d_Z;

// ---------------- mma helpers -------------------------------------------------
__device__ __forceinline__ void ldsm4(unsigned& r0, unsigned& r1,
                                      unsigned& r2, unsigned& r3, unsigned addr) {
    asm volatile("ldmatrix.sync.aligned.m8n8.x4.shared.b16 {%0,%1,%2,%3}, [%4];"
                 : "=r"(r0), "=r"(r1), "=r"(r2), "=r"(r3) : "r"(addr));
}
__device__ __forceinline__ void mma16816(float* c,
                                         unsigned a0, unsigned a1, unsigned a2, unsigned a3,
                                         unsigned b0, unsigned b1) {
    asm volatile("mma.sync.aligned.m16n8k16.row.col.f32.f16.f16.f32 "
                 "{%0,%1,%2,%3}, {%4,%5,%6,%7}, {%8,%9}, {%0,%1,%2,%3};"
                 : "+f"(c[0]), "+f"(c[1]), "+f"(c[2]), "+f"(c[3])
                 : "r"(a0), "r"(a1), "r"(a2), "r"(a3), "r"(b0), "r"(b1));
}

// ---------------- prologue: rowptr + epack + cvtx + cvtw (one launch) --------
__global__ void k_prologue(const int* __restrict__ erows,
                           const int* __restrict__ ecols,
                           const float* __restrict__ evals,
                           const float* __restrict__ x,
                           const float* __restrict__ fc1_w,
                           const float* __restrict__ fc2_w) {
    int bid = blockIdx.x, tid = threadIdx.x;
    if (bid < PB1) {
        int i = bid * 256 + tid;
        if (i >= EE) return;
        d_epack[i] = make_int2(__ldg(ecols + i), __float_as_int(__ldg(evals + i)));
        int r1 = erows[i];
        int r0 = (i == 0) ? -1 : erows[i - 1];
        for (int r = r0 + 1; r <= r1; r++) d_rowptr[r] = i;
        if (i == EE - 1)
            for (int r = r1 + 1; r <= NN; r++) d_rowptr[r] = EE;
    } else if (bid < PB1 + PB2) {
        int i = (bid - PB1) * 256 + tid;
        if (i >= NN * IND / 4) return;
        float4 v = ((const float4*)x)[i];
        __half2 a = __floats2half2_rn(v.x, v.y);
        __half2 b = __floats2half2_rn(v.z, v.w);
        ((uint2*)d_xh)[i] = make_uint2(*(unsigned*)&a, *(unsigned*)&b);
    } else {
        int i = (bid - PB1 - PB2) * 256 + tid;
        if (i < 128 * IND) {
            int n = i / IND, k = i % IND;
            d_w1t[i] = __float2half(fc1_w[k * 128 + n]);
        } else if (i < 128 * (IND + HID)) {
            int j = i - 128 * IND;
            int n = j / HID, k = j % HID;
            d_w2t[j] = __float2half(fc2_w[k * 128 + n]);
        }
    }
}

// ---------------- SpMM 64-wide: 4 edges/warp-iter, uint4 gathers -------------
__global__ void k_spmm64() {
    int row = blockIdx.x * 8 + (threadIdx.x >> 5);
    if (row >= NN) return;
    const int lane = threadIdx.x & 31;
    const int grp = lane >> 3, sub = lane & 7;
    const int s = d_rowptr[row], e = d_rowptr[row + 1];
    float acc[8];
#pragma unroll
    for (int j = 0; j < 8; j++) acc[j] = 0.f;
    float vs = 0.f;
    for (int i = s; i < e; i += 4) {
        int idx = i + grp;
        int2 cv = (idx < e) ? __ldg(&d_epack[idx]) : make_int2(0, 0);
        float v = __int_as_float(cv.y);
        uint4 raw = *(const uint4*)(d_xh + (size_t)cv.x * IND + sub * 8);
        const __half2* hp = (const __half2*)&raw;
#pragma unroll
        for (int j = 0; j < 4; j++) {
            float2 f = __half22float2(hp[j]);
            acc[2 * j]     += v * f.x;
            acc[2 * j + 1] += v * f.y;
        }
        vs += v;
    }
#pragma unroll
    for (int j = 0; j < 8; j++) {
        acc[j] += __shfl_xor_sync(0xFFFFFFFFu, acc[j], 8);
        acc[j] += __shfl_xor_sync(0xFFFFFFFFu, acc[j], 16);
    }
    if (lane < 8) {
        __half2 h0 = __floats2half2_rn(acc[0], acc[1]);
        __half2 h1 = __floats2half2_rn(acc[2], acc[3]);
        __half2 h2 = __floats2half2_rn(acc[4], acc[5]);
        __half2 h3 = __floats2half2_rn(acc[6], acc[7]);
        *(uint4*)(d_A1h + (size_t)row * IND + lane * 8) =
            make_uint4(*(unsigned*)&h0, *(unsigned*)&h1,
                       *(unsigned*)&h2, *(unsigned*)&h3);
    }
    vs += __shfl_xor_sync(0xFFFFFFFFu, vs, 8);
    vs += __shfl_xor_sync(0xFFFFFFFFu, vs, 16);
    if (lane == 0) d_rowsum[row] = vs;
}

// ---------------- SpMM 128-wide: 2 edges/warp-iter, uint4 gathers ------------
__global__ void k_spmm128() {
    int row = blockIdx.x * 8 + (threadIdx.x >> 5);
    if (row >= NN) return;
    const int lane = threadIdx.x & 31;
    const int half = lane >> 4, sub = lane & 15;
    const int s = d_rowptr[row], e = d_rowptr[row + 1];
    float acc[8];
#pragma unroll
    for (int j = 0; j < 8; j++) acc[j] = 0.f;
    int i = s;
    for (; i + 4 <= e; i += 4) {   // unroll 2 iterations for MLP
#pragma unroll
        for (int u = 0; u < 2; u++) {
            int idx = i + u * 2 + half;
            int2 cv = __ldg(&d_epack[idx]);
            float v = __int_as_float(cv.y);
            uint4 raw = *(const uint4*)(d_h1h + (size_t)cv.x * HID + sub * 8);
            const __half2* hp = (const __half2*)&raw;
#pragma unroll
            for (int j = 0; j < 4; j++) {
                float2 f = __half22float2(hp[j]);
                acc[2 * j]     += v * f.x;
                acc[2 * j + 1] += v * f.y;
            }
        }
    }
    for (; i < e; i += 2) {
        int idx = i + half;
        int2 cv = (idx < e) ? __ldg(&d_epack[idx]) : make_int2(0, 0);
        float v = __int_as_float(cv.y);
        uint4 raw = *(const uint4*)(d_h1h + (size_t)cv.x * HID + sub * 8);
        const __half2* hp = (const __half2*)&raw;
#pragma unroll
        for (int j = 0; j < 4; j++) {
            float2 f = __half22float2(hp[j]);
            acc[2 * j]     += v * f.x;
            acc[2 * j + 1] += v * f.y;
        }
    }
#pragma unroll
    for (int j = 0; j < 8; j++)
        acc[j] += __shfl_xor_sync(0xFFFFFFFFu, acc[j], 16);
    if (lane < 16) {
        __half2 h0 = __floats2half2_rn(acc[0], acc[1]);
        __half2 h1 = __floats2half2_rn(acc[2], acc[3]);
        __half2 h2 = __floats2half2_rn(acc[4], acc[5]);
        __half2 h3 = __floats2half2_rn(acc[6], acc[7]);
        *(uint4*)(d_A2h + (size_t)row * HID + lane * 8) =
            make_uint4(*(unsigned*)&h0, *(unsigned*)&h1,
                       *(unsigned*)&h2, *(unsigned*)&h3);
    }
}

// ---------------- tensor-core GEMM (unchanged from R5) -----------------------
template <int K, bool SECOND>
__global__ void __launch_bounds__(256, 2)
k_gemm_mma(const __half* __restrict__ Ag, const __half* __restrict__ Wt,
           const float* __restrict__ bias,
           const float* __restrict__ att_w, const float* __restrict__ att_b) {
    extern __shared__ __align__(16) char smraw[];
    __half* A_sh = (__half*)smraw;
    __half* W_sh = A_sh + 128 * K;
    float* bias_sh = (float*)(W_sh + 128 * K);
    float* aw_sh = bias_sh + 128;
    float* s_sh  = aw_sh + 128;
    float* g_sh  = s_sh + 128;
    float* wmax  = g_sh + 128;
    float* m_sh  = wmax + 8;
    float* z_sh  = m_sh + 1;

    const int tid = threadIdx.x;
    const int r0 = blockIdx.x * 128;
    const int w = tid >> 5, lane = tid & 31;
    const int q = lane & 3, g8 = lane >> 2;

    if (tid < 128) {
        bias_sh[tid] = bias[tid];
        if (SECOND) { aw_sh[tid] = att_w[tid]; g_sh[tid] = 0.f; }
    }
    if (SECOND && tid == 128) z_sh[0] = 0.f;

    constexpr int GPR = K / 8;
    {
        const uint4* src = (const uint4*)Ag;
#pragma unroll
        for (int i = 0; i < 128 * GPR / 256; i++) {
            int idx = i * 256 + tid;
            int row = idx / GPR, g = idx % GPR;
            int gr = r0 + row;
            uint4 v = make_uint4(0, 0, 0, 0);
            if (gr < NN) v = src[(size_t)gr * GPR + g];
            *(uint4*)&A_sh[row * K + ((g ^ (row & 7)) << 3)] = v;
        }
        const uint4* ws = (const uint4*)Wt;
#pragma unroll
        for (int i = 0; i < 128 * GPR / 256; i++) {
            int idx = i * 256 + tid;
            int row = idx / GPR, g = idx % GPR;
            *(uint4*)&W_sh[row * K + ((g ^ (row & 7)) << 3)] = ws[idx];
        }
    }
    __syncthreads();

    unsigned aBase = (unsigned)__cvta_generic_to_shared(A_sh);
    unsigned wBase = (unsigned)__cvta_generic_to_shared(W_sh);

    const int rowA   = w * 16 + ((lane >> 3) & 1) * 8 + (lane & 7);
    const int khalfA = lane >> 4;
    const int rowBoff = ((lane >> 4) & 1) * 8 + (lane & 7);
    const int khalfB  = (lane >> 3) & 1;
    const int l7 = lane & 7;

    float acc[16][4];
#pragma unroll
    for (int t = 0; t < 16; t++)
#pragma unroll
        for (int p = 0; p < 4; p++) acc[t][p] = 0.f;

#pragma unroll
    for (int kc = 0; kc < K; kc += 16) {
        unsigned a0, a1, a2, a3;
        int grpA = (kc >> 3) + khalfA;
        ldsm4(a0, a1, a2, a3,
              aBase + (unsigned)(rowA * K + ((grpA ^ (rowA & 7)) << 3)) * 2u);
        int grpB = (kc >> 3) + khalfB;
#pragma unroll
        for (int jj = 0; jj < 8; jj++) {
            int rowB = jj * 16 + rowBoff;
            unsigned b0, b1, b2, b3;
            ldsm4(b0, b1, b2, b3,
                  wBase + (unsigned)(rowB * K + ((grpB ^ l7) << 3)) * 2u);
            mma16816(acc[2 * jj],     a0, a1, a2, a3, b0, b1);
            mma16816(acc[2 * jj + 1], a0, a1, a2, a3, b2, b3);
        }
    }

    const int lr0 = w * 16 + g8, lr1 = lr0 + 8;
    const int gr0 = r0 + lr0, gr1 = r0 + lr1;
    const float rs0 = (gr0 < NN) ? d_rowsum[gr0] : 0.f;
    const float rs1 = (gr1 < NN) ? d_rowsum[gr1] : 0.f;

#pragma unroll
    for (int t = 0; t < 16; t++) {
#pragma unroll
        for (int p = 0; p < 2; p++) {
            float b = bias_sh[8 * t + 2 * q + p];
            acc[t][p]     = fmaxf(acc[t][p]     + rs0 * b, 0.f);
            acc[t][2 + p] = fmaxf(acc[t][2 + p] + rs1 * b, 0.f);
        }
    }

    if (!SECOND) {
#pragma unroll
        for (int t = 0; t < 16; t++) {
            int col = 8 * t + 2 * q;
            if (gr0 < NN) {
                __half2 h = __floats2half2_rn(acc[t][0], acc[t][1]);
                *(__half2*)&d_h1h[(size_t)gr0 * HID + col] = h;
            }
            if (gr1 < NN) {
                __half2 h = __floats2half2_rn(acc[t][2], acc[t][3]);
                *(__half2*)&d_h1h[(size_t)gr1 * HID + col] = h;
            }
        }
        return;
    } else {
        float sc0 = 0.f, sc1 = 0.f;
#pragma unroll
        for (int t = 0; t < 16; t++) {
            int col = 8 * t + 2 * q;
            if (gr0 < NN) {
                float2 f = __half22float2(*(const __half2*)&d_h1h[(size_t)gr0 * HID + col]);
                acc[t][0] += f.x; acc[t][1] += f.y;
            }
            if (gr1 < NN) {
                float2 f = __half22float2(*(const __half2*)&d_h1h[(size_t)gr1 * HID + col]);
                acc[t][2] += f.x; acc[t][3] += f.y;
            }
            float aw0 = aw_sh[col], aw1 = aw_sh[col + 1];
            sc0 += acc[t][0] * aw0 + acc[t][1] * aw1;
            sc1 += acc[t][2] * aw0 + acc[t][3] * aw1;
        }
        sc0 += __shfl_xor_sync(0xFFFFFFFFu, sc0, 1);
        sc0 += __shfl_xor_sync(0xFFFFFFFFu, sc0, 2);
        sc1 += __shfl_xor_sync(0xFFFFFFFFu, sc1, 1);
        sc1 += __shfl_xor_sync(0xFFFFFFFFu, sc1, 2);
        float ab = att_b[0];
        if (q == 0) {
            s_sh[lr0] = (gr0 < NN) ? (sc0 + ab) : -FLT_MAX;
            s_sh[lr1] = (gr1 < NN) ? (sc1 + ab) : -FLT_MAX;
        }
        __syncthreads();
        {
            float v = s_sh[tid & 127];
#pragma unroll
            for (int off = 16; off; off >>= 1)
                v = fmaxf(v, __shfl_xor_sync(0xFFFFFFFFu, v, off));
            if (lane == 0) wmax[w] = v;
        }
        __syncthreads();
        if (tid == 0) {
            float m = wmax[0];
#pragma unroll
            for (int i = 1; i < 8; i++) m = fmaxf(m, wmax[i]);
            m_sh[0] = m;
        }
        __syncthreads();
        const float mb = m_sh[0];
        const float e0 = __expf(s_sh[lr0] - mb);
        const float e1 = __expf(s_sh[lr1] - mb);
#pragma unroll
        for (int t = 0; t < 16; t++) {
            acc[t][0] = e0 * acc[t][0] + e1 * acc[t][2];
            acc[t][1] = e0 * acc[t][1] + e1 * acc[t][3];
        }
#pragma unroll
        for (int off = 4; off <= 16; off <<= 1) {
#pragma unroll
            for (int t = 0; t < 16; t++) {
                acc[t][0] += __shfl_xor_sync(0xFFFFFFFFu, acc[t][0], off);
                acc[t][1] += __shfl_xor_sync(0xFFFFFFFFu, acc[t][1], off);
            }
        }
        if (lane < 4) {
#pragma unroll
            for (int t = 0; t < 16; t++) {
                atomicAdd(&g_sh[8 * t + 2 * lane],     acc[t][0]);
                atomicAdd(&g_sh[8 * t + 2 * lane + 1], acc[t][1]);
            }
        }
        float ze = (q == 0) ? (e0 + e1) : 0.f;
        ze += __shfl_xor_sync(0xFFFFFFFFu, ze, 4);
        ze += __shfl_xor_sync(0xFFFFFFFFu, ze, 8);
        ze += __shfl_xor_sync(0xFFFFFFFFu, ze, 16);
        if (lane == 0) atomicAdd(z_sh, ze);
        __syncthreads();
        float* pp = d_part + (size_t)blockIdx.x * 130;
        if (tid < 128) pp[tid] = g_sh[tid];
        if (tid == 128) pp[128] = z_sh[0];
        if (tid == 129) pp[129] = m_sh[0];
    }
}

// ---------------- combine ------------------------------------------------------
__global__ void k_combine() {
    __shared__ float red[256];
    __shared__ float Msh;
    int tid = threadIdx.x, j = blockIdx.x;
    float lm = -FLT_MAX;
    for (int b = tid; b < NB; b += 256)
        lm = fmaxf(lm, d_part[(size_t)b * 130 + 129]);
    red[tid] = lm;
    __syncthreads();
    for (int s = 128; s; s >>= 1) {
        if (tid < s) red[tid] = fmaxf(red[tid], red[tid + s]);
        __syncthreads();
    }
    if (tid == 0) Msh = red[0];
    __syncthreads();
    float M = Msh;
    int col = (j < 128) ? j : 128;
    float acc = 0.f;
    for (int b = tid; b < NB; b += 256) {
        float mb = d_part[(size_t)b * 130 + 129];
        acc += __expf(mb - M) * d_part[(size_t)b * 130 + col];
    }
    red[tid] = acc;
    __syncthreads();
    for (int s = 128; s; s >>= 1) {
        if (tid < s) red[tid] += red[tid + s];
        __syncthreads();
    }
    if (tid == 0) {
        if (j < 128) d_g[j] = red[0];
        else d_Z = red[0];
    }
}

// ---------------- final --------------------------------------------------------
__global__ void k_final(const float* __restrict__ cls_w,
                        const float* __restrict__ cls_b,
                        float* __restrict__ out) {
    int c = threadIdx.x;
    if (c < NCLS) {
        float invZ = 1.f / d_Z;
        float acc = cls_b[c];
        for (int k = 0; k < HID; k++)
            acc += (d_g[k] * invZ) * cls_w[k * NCLS + c];
        out[c] = acc;
    }
}

// ---------------- launch ---------------------------------------------------------
extern "C" void kernel_launch(void* const* d_in, const int* in_sizes, int n_in,
                              void* d_out, int out_size) {
    const float* x     = (const float*)d_in[0];
    const int*   erows = (const int*)  d_in[1];
    const int*   ecols = (const int*)  d_in[2];
    const float* evals = (const float*)d_in[3];
    const float* fc1_w = (const float*)d_in[4];
    const float* fc1_b = (const float*)d_in[5];
    const float* fc2_w = (const float*)d_in[6];
    const float* fc2_b = (const float*)d_in[7];
    const float* att_w = (const float*)d_in[8];
    const float* att_b = (const float*)d_in[9];
    const float* cls_w = (const float*)d_in[10];
    const float* cls_b = (const float*)d_in[11];
    float* out = (float*)d_out;

    __half* pA1 = nullptr; __half* pA2 = nullptr;
    __half* pW1 = nullptr; __half* pW2 = nullptr;
    cudaGetSymbolAddress((void**)&pA1, d_A1h);
    cudaGetSymbolAddress((void**)&pA2, d_A2h);
    cudaGetSymbolAddress((void**)&pW1, d_w1t);
    cudaGetSymbolAddress((void**)&pW2, d_w2t);

    const int extras = (128 * 4 + 8 + 2) * 4;
    const int smem1 = 128 * IND * 2 * 2 + extras;
    const int smem2 = 128 * HID * 2 * 2 + extras;
    cudaFuncSetAttribute(k_gemm_mma<IND, false>,
                         cudaFuncAttributeMaxDynamicSharedMemorySize, smem1);
    cudaFuncSetAttribute(k_gemm_mma<HID, true>,
                         cudaFuncAttributeMaxDynamicSharedMemorySize, smem2);

    k_prologue<<<PB1 + PB2 + PB3, 256>>>(erows, ecols, evals, x, fc1_w, fc2_w);
    k_spmm64<<<(NN + 7) / 8, 256>>>();
    k_gemm_mma<IND, false><<<NB, 256, smem1>>>(pA1, pW1, fc1_b, nullptr, nullptr);
    k_spmm128<<<(NN + 7) / 8, 256>>>();
    k_gemm_mma<HID, true><<<NB, 256, smem2>>>(pA2, pW2, fc2_b, att_w, att_b);
    k_combine<<<129, 256>>>();
    k_final<<<1, 32>>>(cls_w, cls_b, out);
}